// round 6
// baseline (speedup 1.0000x reference)
#include <cuda_runtime.h>

// Unpool_LS: 2x2 block learned-sparsity unpool.
// x0: [8,256,256,64] f32, x1: [8,128,128,64] f32
// outputs concatenated into d_out:
//   out0 [8,256,256,64], repl [8,128,128,64], out3 [8,256,256,64]

#define BB   8
#define HH   256
#define WW   256
#define CC   64
#define hh2  128
#define ww2  128
#define C4   (CC / 4)   // 16 float4 per position

// Per-scalar-channel solve: v[4] = block values (row-major: (0,0),(0,1),(1,0),(1,1))
__device__ __forceinline__ void solve1(const float v[4], float x1v,
                                       float o[4], float &repl, float of[4]) {
    // Stable descending rank: rank[i] = #{j : v[j] > v[i]} + #{j < i : v[j] == v[i]}
    int rank[4];
#pragma unroll
    for (int i = 0; i < 4; i++) {
        int r = 0;
#pragma unroll
        for (int j = 0; j < 4; j++) {
            if (j == i) continue;
            bool gt = v[j] > v[i];
            bool tie = (v[j] == v[i]) && (j < i);
            r += (int)(gt || tie);
        }
        rank[i] = r;
    }
    // Sorted-descending values via register scatter
    float sv[4];
#pragma unroll
    for (int i = 0; i < 4; i++) sv[rank[i]] = v[i];

    // avg[k] = (sum_{0..k} sv + x1) / (k+2); first-max argmax (strict >)
    float s = 0.0f;
    float best = 0.0f;
    int kb = 0;
#pragma unroll
    for (int k = 0; k < 4; k++) {
        s += sv[k];
        float avg = (s + x1v) / (float)(k + 2);
        if (k == 0) { best = avg; kb = 0; }
        else if (avg > best) { best = avg; kb = k; }
    }
    repl = best;
    float frac = (float)(kb + 1) / (float)(kb + 2);
#pragma unroll
    for (int i = 0; i < 4; i++) {
        bool m = (rank[i] <= kb);
        o[i]  = m ? best : v[i];
        of[i] = m ? frac : 1.0f;
    }
}

__global__ void __launch_bounds__(256)
unpool_ls_kernel(const float4 *__restrict__ x0,
                 const float4 *__restrict__ x1,
                 float4 *__restrict__ out0,
                 float4 *__restrict__ out1,
                 float4 *__restrict__ out2) {
    int t = blockIdx.x * blockDim.x + threadIdx.x;   // [0, 131072*16)
    int cq  = t & (C4 - 1);      // channel quad 0..15
    int blk = t >> 4;            // linear (b,h,w) block index, 0..131071

    int w = blk & (ww2 - 1);
    int h = (blk >> 7) & (hh2 - 1);
    int b = blk >> 14;

    int pos = ((b * HH + 2 * h) * WW + 2 * w);       // position index in x0
    int i00 = pos * C4 + cq;
    int i01 = i00 + C4;
    int i10 = i00 + WW * C4;
    int i11 = i10 + C4;

    // Front-batched loads (MLP for latency hiding)
    float4 a0 = x0[i00];
    float4 a1 = x0[i01];
    float4 a2 = x0[i10];
    float4 a3 = x0[i11];
    float4 pv = x1[blk * C4 + cq];

    float v0[4] = {a0.x, a0.y, a0.z, a0.w};
    float v1[4] = {a1.x, a1.y, a1.z, a1.w};
    float v2[4] = {a2.x, a2.y, a2.z, a2.w};
    float v3[4] = {a3.x, a3.y, a3.z, a3.w};
    float pp[4] = {pv.x, pv.y, pv.z, pv.w};

    float o0[4], o1[4], o2[4], o3[4];
    float f0[4], f1[4], f2[4], f3[4];
    float rr[4];

#pragma unroll
    for (int ln = 0; ln < 4; ln++) {
        float v[4] = {v0[ln], v1[ln], v2[ln], v3[ln]};
        float o[4], of[4], rp;
        solve1(v, pp[ln], o, rp, of);
        o0[ln] = o[0]; o1[ln] = o[1]; o2[ln] = o[2]; o3[ln] = o[3];
        f0[ln] = of[0]; f1[ln] = of[1]; f2[ln] = of[2]; f3[ln] = of[3];
        rr[ln] = rp;
    }

    out0[i00] = make_float4(o0[0], o0[1], o0[2], o0[3]);
    out0[i01] = make_float4(o1[0], o1[1], o1[2], o1[3]);
    out0[i10] = make_float4(o2[0], o2[1], o2[2], o2[3]);
    out0[i11] = make_float4(o3[0], o3[1], o3[2], o3[3]);

    out1[blk * C4 + cq] = make_float4(rr[0], rr[1], rr[2], rr[3]);

    out2[i00] = make_float4(f0[0], f0[1], f0[2], f0[3]);
    out2[i01] = make_float4(f1[0], f1[1], f1[2], f1[3]);
    out2[i10] = make_float4(f2[0], f2[1], f2[2], f2[3]);
    out2[i11] = make_float4(f3[0], f3[1], f3[2], f3[3]);
}

extern "C" void kernel_launch(void* const* d_in, const int* in_sizes, int n_in,
                              void* d_out, int out_size) {
    const float* x0 = (const float*)d_in[0];
    const float* x1 = (const float*)d_in[1];
    float* out = (float*)d_out;

    const size_t N0 = (size_t)BB * HH * WW * CC;     // 33554432
    const size_t N1 = (size_t)BB * hh2 * ww2 * CC;   // 8388608

    float* out0 = out;
    float* out1 = out + N0;
    float* out2 = out + N0 + N1;

    const int total_threads = (BB * hh2 * ww2) * C4; // 131072 * 16 = 2097152
    const int block = 256;
    const int grid = total_threads / block;          // 8192

    unpool_ls_kernel<<<grid, block>>>((const float4*)x0, (const float4*)x1,
                                      (float4*)out0, (float4*)out1, (float4*)out2);
}